// round 14
// baseline (speedup 1.0000x reference)
#include <cuda_runtime.h>
#include <cstdint>

#define BATCH   131072
#define BK20    2621440u    // BATCH * 20

// JAX partitionable threefry random_bits(32):
//   (b1, b2) = threefry2x32(key=(0,42), ctr=(0,i));  bits = b1 ^ b2
// keep ⟺ MSB(bits) == 0.   (validated R7/R10)
__device__ __forceinline__ uint32_t tf_bits(uint32_t ctr) {
    const uint32_t ks1 = 42u;
    const uint32_t ks2 = 0x1BD11BDAu ^ 42u;
    uint32_t x0 = 0u;
    uint32_t x1 = ctr + ks1;
#define TF_R4(a, b, c, d)                                          \
    x0 += x1; x1 = __funnelshift_l(x1, x1, a); x1 ^= x0;           \
    x0 += x1; x1 = __funnelshift_l(x1, x1, b); x1 ^= x0;           \
    x0 += x1; x1 = __funnelshift_l(x1, x1, c); x1 ^= x0;           \
    x0 += x1; x1 = __funnelshift_l(x1, x1, d); x1 ^= x0;
    TF_R4(13, 15, 26, 6);   x0 += ks1; x1 += ks2 + 1u;
    TF_R4(17, 29, 16, 24);  x0 += ks2; x1 += 2u;
    TF_R4(13, 15, 26, 6);   /* ks0 */  x1 += ks1 + 3u;
    TF_R4(17, 29, 16, 24);  x0 += ks1; x1 += ks2 + 4u;
    TF_R4(13, 15, 26, 6);   x0 += ks2; x1 += 5u;
#undef TF_R4
    return x0 ^ x1;
}

// 2 threads per batch element: lane pair (tid, tid^1).
// parity p: hd-half [p*30, p*30+30), output-half [p*10, p*10+10).
__global__ __launch_bounds__(256, 4)
void Net_69655779606932_kernel(const float* __restrict__ x,
                               const float* __restrict__ W1,
                               const float* __restrict__ b1,
                               const float* __restrict__ Wh,
                               const float* __restrict__ bh,
                               float* __restrict__ out)
{
    __shared__ __align__(16) float sW1[20][64];      // [d][j], halves at col 0 / 32
    __shared__ __align__(16) float sb1[64];          // halves at 0 / 32
    __shared__ __align__(16) float sWh[8][60][20];   // [local_head][hd][o]
    __shared__ __align__(16) float sbh[8][20];       // staged as bh * 0.5f

    const int tid = threadIdx.x;
    const int p   = tid & 1;
    const int e   = blockIdx.x * 128 + (tid >> 1);

    // ---- stage trunk weights, column-split-padded for aligned half reads ----
    for (int i = tid; i < 1200; i += 256) {
        int j = i / 20, d = i % 20;                  // W1 is [60][20]: (j, d)
        sW1[d][j + (j >= 30 ? 2 : 0)] = W1[i];
    }
    if (tid < 60) sb1[tid + (tid >= 30 ? 2 : 0)] = b1[tid];
    __syncthreads();

    // ---- trunk half: hh[j] = relu(b1 + sum_d x_d * W1[j,d]), j in my 30 ----
    float hh[30];
    {
        float xr[20];
        const float4* xv = reinterpret_cast<const float4*>(x + (size_t)e * 20);
#pragma unroll
        for (int q = 0; q < 5; q++) {
            float4 t = xv[q];
            xr[4 * q] = t.x; xr[4 * q + 1] = t.y; xr[4 * q + 2] = t.z; xr[4 * q + 3] = t.w;
        }
        const float* bp = &sb1[p * 32];
#pragma unroll
        for (int q = 0; q < 7; q++) {
            float4 t = reinterpret_cast<const float4*>(bp)[q];
            hh[4 * q] = t.x; hh[4 * q + 1] = t.y; hh[4 * q + 2] = t.z; hh[4 * q + 3] = t.w;
        }
        float2 t2 = *reinterpret_cast<const float2*>(bp + 28);
        hh[28] = t2.x; hh[29] = t2.y;
#pragma unroll
        for (int d = 0; d < 20; d++) {
            float xd = xr[d];
            const float* wr = &sW1[d][p * 32];
#pragma unroll
            for (int q = 0; q < 7; q++) {
                float4 w = reinterpret_cast<const float4*>(wr)[q];
                hh[4 * q + 0] = fmaf(xd, w.x, hh[4 * q + 0]);
                hh[4 * q + 1] = fmaf(xd, w.y, hh[4 * q + 1]);
                hh[4 * q + 2] = fmaf(xd, w.z, hh[4 * q + 2]);
                hh[4 * q + 3] = fmaf(xd, w.w, hh[4 * q + 3]);
            }
            float2 w2 = *reinterpret_cast<const float2*>(wr + 28);
            hh[28] = fmaf(xd, w2.x, hh[28]);
            hh[29] = fmaf(xd, w2.y, hh[29]);
        }
    }
    // pack relu'd hidden pairs: hh2[t] = (hh[2t], hh[2t+1])
    uint64_t hh2[15];
#pragma unroll
    for (int t = 0; t < 15; t++) {
        uint32_t lo = __float_as_uint(fmaxf(hh[2 * t], 0.0f));
        uint32_t hi = __float_as_uint(fmaxf(hh[2 * t + 1], 0.0f));
        asm("mov.b64 %0, {%1, %2};" : "=l"(hh2[t]) : "r"(lo), "r"(hi));
    }

    // ---- 40 heads in 5 phases of 8 ----
    for (int ph = 0; ph < 5; ph++) {
        __syncthreads();
        for (int i = tid; i < 8 * 1200; i += 256) {
            int lh = i / 1200, rem = i % 1200;       // rem = o*60 + hd
            int o  = rem / 60, hd = rem % 60;
            sWh[lh][hd][o] = Wh[(ph * 8 + lh) * 1200 + rem];
        }
        for (int i = tid; i < 160; i += 256)
            sbh[i / 20][i % 20] = 0.5f * bh[ph * 160 + i];   // halved bias
        __syncthreads();

#pragma unroll 1
        for (int lh = 0; lh < 8; lh++) {
            const int k = ph * 8 + lh;

            // packed accumulators init with bias/2 (both lanes -> sums to bias once)
            uint64_t acc2[10];
            {
                const ulonglong2* bp2 = reinterpret_cast<const ulonglong2*>(&sbh[lh][0]);
#pragma unroll
                for (int q = 0; q < 5; q++) {
                    ulonglong2 t = bp2[q];
                    acc2[2 * q] = t.x; acc2[2 * q + 1] = t.y;
                }
            }

#pragma unroll
            for (int t = 0; t < 15; t++) {
                uint32_t lo, hi;
                asm("mov.b64 {%0, %1}, %2;" : "=r"(lo), "=r"(hi) : "l"(hh2[t]));
                uint64_t hva, hvb;
                asm("mov.b64 %0, {%1, %1};" : "=l"(hva) : "r"(lo));
                asm("mov.b64 %0, {%1, %1};" : "=l"(hvb) : "r"(hi));
                const ulonglong2* wa =
                    reinterpret_cast<const ulonglong2*>(&sWh[lh][p * 30 + 2 * t][0]);
                const ulonglong2* wb =
                    reinterpret_cast<const ulonglong2*>(&sWh[lh][p * 30 + 2 * t + 1][0]);
#pragma unroll
                for (int q = 0; q < 5; q++) {
                    ulonglong2 A = wa[q];
                    ulonglong2 B = wb[q];
                    asm("fma.rn.f32x2 %0, %1, %2, %0;" : "+l"(acc2[2 * q])     : "l"(hva), "l"(A.x));
                    asm("fma.rn.f32x2 %0, %1, %2, %0;" : "+l"(acc2[2 * q + 1]) : "l"(hva), "l"(A.y));
                    asm("fma.rn.f32x2 %0, %1, %2, %0;" : "+l"(acc2[2 * q])     : "l"(hvb), "l"(B.x));
                    asm("fma.rn.f32x2 %0, %1, %2, %0;" : "+l"(acc2[2 * q + 1]) : "l"(hvb), "l"(B.y));
                }
            }

            // cross-lane reduction: partner holds the other hd-half
#pragma unroll
            for (int q = 0; q < 10; q++) {
                uint64_t other = __shfl_xor_sync(0xFFFFFFFFu, acc2[q], 1);
                asm("add.rn.f32x2 %0, %0, %1;" : "+l"(acc2[q]) : "l"(other));
            }

            const uint32_t cbase = (uint32_t)k * BK20 + (uint32_t)e * 20u + (uint32_t)(p * 10);
            float* op = out + (size_t)k * BK20 + (size_t)e * 20 + p * 10;

#pragma unroll
            for (int j = 0; j < 5; j++) {
                uint64_t own = p ? acc2[j + 5] : acc2[j];
                uint32_t lo, hi;
                asm("mov.b64 {%0, %1}, %2;" : "=r"(lo), "=r"(hi) : "l"(own));
                uint32_t r0 = tf_bits(cbase + 2u * j);
                uint32_t r1 = tf_bits(cbase + 2u * j + 1u);
                uint32_t f0 = ((~r0) & 0x80000000u) >> 1;    // 0x40000000 = 2.0f or 0
                uint32_t f1 = ((~r1) & 0x80000000u) >> 1;
                float v0 = fmaxf(__uint_as_float(lo), 0.0f) * __uint_as_float(f0);
                float v1 = fmaxf(__uint_as_float(hi), 0.0f) * __uint_as_float(f1);
                *reinterpret_cast<float2*>(op + 2 * j) = make_float2(v0, v1);
            }
        }
    }
}

extern "C" void kernel_launch(void* const* d_in, const int* in_sizes, int n_in,
                              void* d_out, int out_size) {
    const float* x  = (const float*)d_in[0];
    const float* W1 = (const float*)d_in[1];
    const float* b1 = (const float*)d_in[2];
    const float* Wh = (const float*)d_in[3];
    const float* bh = (const float*)d_in[4];
    // 2 threads per element: 262144 threads, 256/block -> 1024 blocks
    Net_69655779606932_kernel<<<(BATCH * 2) / 256, 256>>>(x, W1, b1, Wh, bh, (float*)d_out);
}

// round 15
// speedup vs baseline: 1.6466x; 1.6466x over previous
#include <cuda_runtime.h>
#include <cstdint>

#define BATCH   131072
#define BK20    2621440u    // BATCH * 20

// JAX partitionable threefry random_bits(32):
//   (b1, b2) = threefry2x32(key=(0,42), ctr=(0,i));  bits = b1 ^ b2
// keep ⟺ MSB(bits) == 0.   (validated R7/R10/R14)
__device__ __forceinline__ uint32_t tf_bits(uint32_t ctr) {
    const uint32_t ks1 = 42u;
    const uint32_t ks2 = 0x1BD11BDAu ^ 42u;
    uint32_t x0 = 0u;
    uint32_t x1 = ctr + ks1;
#define TF_R4(a, b, c, d)                                          \
    x0 += x1; x1 = __funnelshift_l(x1, x1, a); x1 ^= x0;           \
    x0 += x1; x1 = __funnelshift_l(x1, x1, b); x1 ^= x0;           \
    x0 += x1; x1 = __funnelshift_l(x1, x1, c); x1 ^= x0;           \
    x0 += x1; x1 = __funnelshift_l(x1, x1, d); x1 ^= x0;
    TF_R4(13, 15, 26, 6);   x0 += ks1; x1 += ks2 + 1u;
    TF_R4(17, 29, 16, 24);  x0 += ks2; x1 += 2u;
    TF_R4(13, 15, 26, 6);   /* ks0 */  x1 += ks1 + 3u;
    TF_R4(17, 29, 16, 24);  x0 += ks1; x1 += ks2 + 4u;
    TF_R4(13, 15, 26, 6);   x0 += ks2; x1 += 5u;
#undef TF_R4
    return x0 ^ x1;
}

// 2 threads per batch element: lane pair (tid, tid^1).
// parity p: hd-half [p*30, p*30+30), output-half [p*10, p*10+10).
__global__ __launch_bounds__(256, 3)
void Net_69655779606932_kernel(const float* __restrict__ x,
                               const float* __restrict__ W1,
                               const float* __restrict__ b1,
                               const float* __restrict__ Wh,
                               const float* __restrict__ bh,
                               float* __restrict__ out)
{
    __shared__ __align__(16) float sW1[20][64];      // [d][j], halves at col 0 / 32
    __shared__ __align__(16) float sb1[64];          // halves at 0 / 32
    __shared__ __align__(16) float sWh[8][60][20];   // [local_head][hd][o]
    __shared__ __align__(16) float sbh[8][20];       // staged as bh * 0.5f

    const int tid = threadIdx.x;
    const int p   = tid & 1;
    const int e   = blockIdx.x * 128 + (tid >> 1);

    // ---- stage trunk weights, column-split-padded for aligned half reads ----
    for (int i = tid; i < 1200; i += 256) {
        int j = i / 20, d = i % 20;                  // W1 is [60][20]: (j, d)
        sW1[d][j + (j >= 30 ? 2 : 0)] = W1[i];
    }
    if (tid < 60) sb1[tid + (tid >= 30 ? 2 : 0)] = b1[tid];
    __syncthreads();

    // ---- trunk half: hh[j] = relu(b1 + sum_d x_d * W1[j,d]), j in my 30 ----
    float hh[30];
    {
        float xr[20];
        const float4* xv = reinterpret_cast<const float4*>(x + (size_t)e * 20);
#pragma unroll
        for (int q = 0; q < 5; q++) {
            float4 t = xv[q];
            xr[4 * q] = t.x; xr[4 * q + 1] = t.y; xr[4 * q + 2] = t.z; xr[4 * q + 3] = t.w;
        }
        const float* bp = &sb1[p * 32];
#pragma unroll
        for (int q = 0; q < 7; q++) {
            float4 t = reinterpret_cast<const float4*>(bp)[q];
            hh[4 * q] = t.x; hh[4 * q + 1] = t.y; hh[4 * q + 2] = t.z; hh[4 * q + 3] = t.w;
        }
        float2 t2 = *reinterpret_cast<const float2*>(bp + 28);
        hh[28] = t2.x; hh[29] = t2.y;
#pragma unroll
        for (int d = 0; d < 20; d++) {
            float xd = xr[d];
            const float* wr = &sW1[d][p * 32];
#pragma unroll
            for (int q = 0; q < 7; q++) {
                float4 w = reinterpret_cast<const float4*>(wr)[q];
                hh[4 * q + 0] = fmaf(xd, w.x, hh[4 * q + 0]);
                hh[4 * q + 1] = fmaf(xd, w.y, hh[4 * q + 1]);
                hh[4 * q + 2] = fmaf(xd, w.z, hh[4 * q + 2]);
                hh[4 * q + 3] = fmaf(xd, w.w, hh[4 * q + 3]);
            }
            float2 w2 = *reinterpret_cast<const float2*>(wr + 28);
            hh[28] = fmaf(xd, w2.x, hh[28]);
            hh[29] = fmaf(xd, w2.y, hh[29]);
        }
    }
#pragma unroll
    for (int j = 0; j < 30; j++) hh[j] = fmaxf(hh[j], 0.0f);

    // ---- 40 heads in 5 phases of 8 ----
    for (int ph = 0; ph < 5; ph++) {
        __syncthreads();
        for (int i = tid; i < 8 * 1200; i += 256) {
            int lh = i / 1200, rem = i % 1200;       // rem = o*60 + hd
            int o  = rem / 60, hd = rem % 60;
            sWh[lh][hd][o] = Wh[(ph * 8 + lh) * 1200 + rem];
        }
        for (int i = tid; i < 160; i += 256)
            sbh[i / 20][i % 20] = 0.5f * bh[ph * 160 + i];   // halved bias
        __syncthreads();

#pragma unroll 1
        for (int lh = 0; lh < 8; lh++) {
            const int k = ph * 8 + lh;

            // packed accumulators init with bias/2 (both lanes -> sums to bias once)
            uint64_t acc2[10];
            {
                const ulonglong2* bp2 = reinterpret_cast<const ulonglong2*>(&sbh[lh][0]);
#pragma unroll
                for (int q = 0; q < 5; q++) {
                    ulonglong2 t = bp2[q];
                    acc2[2 * q] = t.x; acc2[2 * q + 1] = t.y;
                }
            }

#pragma unroll
            for (int t = 0; t < 15; t++) {
                uint64_t hva, hvb;
                asm("mov.b64 %0, {%1, %1};" : "=l"(hva) : "r"(__float_as_uint(hh[2 * t])));
                asm("mov.b64 %0, {%1, %1};" : "=l"(hvb) : "r"(__float_as_uint(hh[2 * t + 1])));
                const ulonglong2* wa =
                    reinterpret_cast<const ulonglong2*>(&sWh[lh][p * 30 + 2 * t][0]);
                const ulonglong2* wb =
                    reinterpret_cast<const ulonglong2*>(&sWh[lh][p * 30 + 2 * t + 1][0]);
#pragma unroll
                for (int q = 0; q < 5; q++) {
                    ulonglong2 A = wa[q];
                    ulonglong2 B = wb[q];
                    asm("fma.rn.f32x2 %0, %1, %2, %0;" : "+l"(acc2[2 * q])     : "l"(hva), "l"(A.x));
                    asm("fma.rn.f32x2 %0, %1, %2, %0;" : "+l"(acc2[2 * q + 1]) : "l"(hva), "l"(A.y));
                    asm("fma.rn.f32x2 %0, %1, %2, %0;" : "+l"(acc2[2 * q])     : "l"(hvb), "l"(B.x));
                    asm("fma.rn.f32x2 %0, %1, %2, %0;" : "+l"(acc2[2 * q + 1]) : "l"(hvb), "l"(B.y));
                }
            }

            // cross-lane reduction: partner holds the other hd-half
#pragma unroll
            for (int q = 0; q < 10; q++) {
                uint64_t other = __shfl_xor_sync(0xFFFFFFFFu, acc2[q], 1);
                asm("add.rn.f32x2 %0, %0, %1;" : "+l"(acc2[q]) : "l"(other));
            }

            const uint32_t cbase = (uint32_t)k * BK20 + (uint32_t)e * 20u + (uint32_t)(p * 10);
            float* op = out + (size_t)k * BK20 + (size_t)e * 20 + p * 10;

#pragma unroll
            for (int j = 0; j < 5; j++) {
                uint64_t own = p ? acc2[j + 5] : acc2[j];
                uint32_t lo, hi;
                asm("mov.b64 {%0, %1}, %2;" : "=r"(lo), "=r"(hi) : "l"(own));
                uint32_t r0 = tf_bits(cbase + 2u * j);
                uint32_t r1 = tf_bits(cbase + 2u * j + 1u);
                uint32_t f0 = ((~r0) & 0x80000000u) >> 1;    // 0x40000000 = 2.0f or 0
                uint32_t f1 = ((~r1) & 0x80000000u) >> 1;
                float v0 = fmaxf(__uint_as_float(lo), 0.0f) * __uint_as_float(f0);
                float v1 = fmaxf(__uint_as_float(hi), 0.0f) * __uint_as_float(f1);
                *reinterpret_cast<float2*>(op + 2 * j) = make_float2(v0, v1);
            }
        }
    }
}

extern "C" void kernel_launch(void* const* d_in, const int* in_sizes, int n_in,
                              void* d_out, int out_size) {
    const float* x  = (const float*)d_in[0];
    const float* W1 = (const float*)d_in[1];
    const float* b1 = (const float*)d_in[2];
    const float* Wh = (const float*)d_in[3];
    const float* bh = (const float*)d_in[4];
    // 2 threads per element: 262144 threads, 256/block -> 1024 blocks
    Net_69655779606932_kernel<<<(BATCH * 2) / 256, 256>>>(x, W1, b1, Wh, bh, (float*)d_out);
}